// round 6
// baseline (speedup 1.0000x reference)
#include <cuda_runtime.h>

// CrossNet collapsed form (exact algebra, no approximation):
//   xi_l = c_l * x0 + d_l,  d_l = B0+..+B_{l-1} (row-independent)
//   t_l  = x0 . w_l
//   c_{l+1} = c_l * (1 + t_l) + e_l,  e_l = d_l . w_l
//   out  = c_3 * x0 + D,  D = B0+B1+B2
//
// Single persistent kernel: each block computes e1,e2,D itself during the
// staging phase (W/B are L2-resident), then grid-strides warps over rows.
// One wave (444 blocks), W staged once per block, x0/out streamed once.

#define CN_DIM 1024
#define CN_ORDER 3
#define CN_THREADS 256
#define CN_WARPS (CN_THREADS / 32)
#define CN_VEC (CN_DIM / 4)        // 256 float4 per row
#define CN_V_PER_LANE 8            // 256 / 32 lanes
#define CN_BLOCKS 444              // 148 SMs * 3 blocks

__global__ __launch_bounds__(CN_THREADS, 3)
void crossnet_persistent_kernel(const float* __restrict__ x0,
                                const float* __restrict__ W,
                                const float* __restrict__ B,
                                float* __restrict__ out,
                                int batch)
{
    __shared__ float sW[CN_ORDER * CN_DIM];
    __shared__ float sD[CN_DIM];
    __shared__ float sE[2];
    __shared__ float red1[CN_WARPS];
    __shared__ float red2[CN_WARPS];

    const int tid  = threadIdx.x;
    const int warp = tid >> 5;
    const int lane = tid & 31;

    // ---- staging: W -> smem; compute D, e1, e2 from B/W (L2-hit reads) ----
    {
        // CN_VEC == CN_THREADS: each thread owns exactly one float4 index.
        const int i = tid;
        const float4* gW = (const float4*)W;
        float4 w0 = gW[i];
        float4 w1 = gW[CN_VEC + i];
        float4 w2 = gW[2 * CN_VEC + i];
        ((float4*)sW)[i]              = w0;
        ((float4*)sW)[CN_VEC + i]     = w1;
        ((float4*)sW)[2 * CN_VEC + i] = w2;

        const float4* gB = (const float4*)B;
        float4 b0 = gB[i];
        float4 b1 = gB[CN_VEC + i];
        float4 b2 = gB[2 * CN_VEC + i];

        // e1 = B0 . w1
        float p1 = 0.f;
        p1 = fmaf(b0.x, w1.x, p1); p1 = fmaf(b0.y, w1.y, p1);
        p1 = fmaf(b0.z, w1.z, p1); p1 = fmaf(b0.w, w1.w, p1);
        // d2 = B0 + B1 ; e2 = d2 . w2
        float4 d2 = make_float4(b0.x + b1.x, b0.y + b1.y, b0.z + b1.z, b0.w + b1.w);
        float p2 = 0.f;
        p2 = fmaf(d2.x, w2.x, p2); p2 = fmaf(d2.y, w2.y, p2);
        p2 = fmaf(d2.z, w2.z, p2); p2 = fmaf(d2.w, w2.w, p2);
        // D = d2 + B2
        ((float4*)sD)[i] = make_float4(d2.x + b2.x, d2.y + b2.y,
                                       d2.z + b2.z, d2.w + b2.w);

        #pragma unroll
        for (int off = 16; off > 0; off >>= 1) {
            p1 += __shfl_xor_sync(0xffffffffu, p1, off);
            p2 += __shfl_xor_sync(0xffffffffu, p2, off);
        }
        if (lane == 0) { red1[warp] = p1; red2[warp] = p2; }
    }
    __syncthreads();
    if (tid == 0) {
        float e1 = 0.f, e2 = 0.f;
        #pragma unroll
        for (int w = 0; w < CN_WARPS; w++) { e1 += red1[w]; e2 += red2[w]; }
        sE[0] = e1; sE[1] = e2;
    }
    __syncthreads();

    const float e1 = sE[0], e2 = sE[1];
    const float4* w0 = (const float4*)(sW + 0 * CN_DIM);
    const float4* w1 = (const float4*)(sW + 1 * CN_DIM);
    const float4* w2 = (const float4*)(sW + 2 * CN_DIM);
    const float4* dv = (const float4*)sD;

    // ---- persistent row loop: warp-per-row, grid-stride ----
    const int gwarp   = blockIdx.x * CN_WARPS + warp;
    const int nwarps  = gridDim.x * CN_WARPS;

    for (int row = gwarp; row < batch; row += nwarps) {
        const float4* __restrict__ xrow = (const float4*)(x0 + (size_t)row * CN_DIM);

        float4 x[CN_V_PER_LANE];
        #pragma unroll
        for (int i = 0; i < CN_V_PER_LANE; i++)
            x[i] = xrow[i * 32 + lane];

        // three independent dots, 2 accumulators each for ILP
        float t0a = 0.f, t0b = 0.f, t1a = 0.f, t1b = 0.f, t2a = 0.f, t2b = 0.f;
        #pragma unroll
        for (int i = 0; i < CN_V_PER_LANE; i += 2) {
            float4 xa = x[i], xb = x[i + 1];
            float4 wa, wb;
            wa = w0[i * 32 + lane]; wb = w0[(i + 1) * 32 + lane];
            t0a = fmaf(xa.x, wa.x, t0a); t0a = fmaf(xa.y, wa.y, t0a);
            t0a = fmaf(xa.z, wa.z, t0a); t0a = fmaf(xa.w, wa.w, t0a);
            t0b = fmaf(xb.x, wb.x, t0b); t0b = fmaf(xb.y, wb.y, t0b);
            t0b = fmaf(xb.z, wb.z, t0b); t0b = fmaf(xb.w, wb.w, t0b);
            wa = w1[i * 32 + lane]; wb = w1[(i + 1) * 32 + lane];
            t1a = fmaf(xa.x, wa.x, t1a); t1a = fmaf(xa.y, wa.y, t1a);
            t1a = fmaf(xa.z, wa.z, t1a); t1a = fmaf(xa.w, wa.w, t1a);
            t1b = fmaf(xb.x, wb.x, t1b); t1b = fmaf(xb.y, wb.y, t1b);
            t1b = fmaf(xb.z, wb.z, t1b); t1b = fmaf(xb.w, wb.w, t1b);
            wa = w2[i * 32 + lane]; wb = w2[(i + 1) * 32 + lane];
            t2a = fmaf(xa.x, wa.x, t2a); t2a = fmaf(xa.y, wa.y, t2a);
            t2a = fmaf(xa.z, wa.z, t2a); t2a = fmaf(xa.w, wa.w, t2a);
            t2b = fmaf(xb.x, wb.x, t2b); t2b = fmaf(xb.y, wb.y, t2b);
            t2b = fmaf(xb.z, wb.z, t2b); t2b = fmaf(xb.w, wb.w, t2b);
        }
        float t0 = t0a + t0b, t1 = t1a + t1b, t2 = t2a + t2b;

        #pragma unroll
        for (int off = 16; off > 0; off >>= 1) {
            t0 += __shfl_xor_sync(0xffffffffu, t0, off);
            t1 += __shfl_xor_sync(0xffffffffu, t1, off);
            t2 += __shfl_xor_sync(0xffffffffu, t2, off);
        }

        float c = 1.0f + t0;              // c1
        c = fmaf(c, t1, c) + e1;          // c2
        c = fmaf(c, t2, c) + e2;          // c3

        float4* __restrict__ orow = (float4*)(out + (size_t)row * CN_DIM);
        #pragma unroll
        for (int i = 0; i < CN_V_PER_LANE; i++) {
            float4 d = dv[i * 32 + lane];
            float4 o;
            o.x = fmaf(c, x[i].x, d.x);
            o.y = fmaf(c, x[i].y, d.y);
            o.z = fmaf(c, x[i].z, d.z);
            o.w = fmaf(c, x[i].w, d.w);
            orow[i * 32 + lane] = o;
        }
    }
}

extern "C" void kernel_launch(void* const* d_in, const int* in_sizes, int n_in,
                              void* d_out, int out_size)
{
    const float* x0 = (const float*)d_in[0];
    const float* W  = (const float*)d_in[1];
    const float* B  = (const float*)d_in[2];
    float* out      = (float*)d_out;

    const int batch = in_sizes[0] / CN_DIM;

    crossnet_persistent_kernel<<<CN_BLOCKS, CN_THREADS>>>(x0, W, B, out, batch);
}

// round 7
// speedup vs baseline: 1.5930x; 1.5930x over previous
#include <cuda_runtime.h>

// CrossNet collapsed form (exact algebra):
//   xi_l = c_l * x0 + d_l,  d_l = B0+..+B_{l-1} (row-independent)
//   t_l  = x0 . w_l
//   c_{l+1} = c_l * (1 + t_l) + e_l,  e_l = d_l . w_l
//   out  = c_3 * x0 + D,  D = B0+B1+B2
//
// Single kernel, block-per-8-rows (wave parallelism hides DRAM latency;
// persistent grid-stride was measured WORSE — serializes rows in-warp).
// Each block computes e1,e2,D itself during staging (W/B are L2-resident),
// so there is no prep kernel and only one launch.

#define CN_DIM 1024
#define CN_ORDER 3
#define CN_ROWS_PER_BLOCK 8
#define CN_THREADS 256
#define CN_WARPS (CN_THREADS / 32)
#define CN_VEC (CN_DIM / 4)        // 256 float4 per row
#define CN_V_PER_LANE 8            // 256 / 32 lanes

__global__ __launch_bounds__(CN_THREADS, 3)
void crossnet_fused_kernel(const float* __restrict__ x0,
                           const float* __restrict__ W,
                           const float* __restrict__ B,
                           float* __restrict__ out,
                           int batch)
{
    __shared__ float sW[CN_ORDER * CN_DIM];
    __shared__ float sD[CN_DIM];
    __shared__ float sE[2];
    __shared__ float red1[CN_WARPS];
    __shared__ float red2[CN_WARPS];

    const int tid  = threadIdx.x;
    const int warp = tid >> 5;
    const int lane = tid & 31;
    const int row  = blockIdx.x * CN_ROWS_PER_BLOCK + warp;
    const bool active = (row < batch);

    // Fire this warp's x0 row loads FIRST: 8 independent LDG.128 per lane
    // overlap the staging + barrier below.
    const float4* __restrict__ xrow =
        (const float4*)(x0 + (size_t)(active ? row : 0) * CN_DIM);
    float4 x[CN_V_PER_LANE];
    #pragma unroll
    for (int i = 0; i < CN_V_PER_LANE; i++)
        x[i] = xrow[i * 32 + lane];

    // ---- staging: W -> smem; compute D, e1, e2 from B/W (L2-hit reads) ----
    {
        const int i = tid;  // CN_VEC == CN_THREADS: one float4 per thread
        const float4* gW = (const float4*)W;
        float4 w0 = gW[i];
        float4 w1 = gW[CN_VEC + i];
        float4 w2 = gW[2 * CN_VEC + i];
        ((float4*)sW)[i]              = w0;
        ((float4*)sW)[CN_VEC + i]     = w1;
        ((float4*)sW)[2 * CN_VEC + i] = w2;

        const float4* gB = (const float4*)B;
        float4 b0 = gB[i];
        float4 b1 = gB[CN_VEC + i];
        float4 b2 = gB[2 * CN_VEC + i];

        // e1 = B0 . w1
        float p1 = 0.f;
        p1 = fmaf(b0.x, w1.x, p1); p1 = fmaf(b0.y, w1.y, p1);
        p1 = fmaf(b0.z, w1.z, p1); p1 = fmaf(b0.w, w1.w, p1);
        // d2 = B0 + B1 ; e2 = d2 . w2
        float4 d2 = make_float4(b0.x + b1.x, b0.y + b1.y, b0.z + b1.z, b0.w + b1.w);
        float p2 = 0.f;
        p2 = fmaf(d2.x, w2.x, p2); p2 = fmaf(d2.y, w2.y, p2);
        p2 = fmaf(d2.z, w2.z, p2); p2 = fmaf(d2.w, w2.w, p2);
        // D = d2 + B2
        ((float4*)sD)[i] = make_float4(d2.x + b2.x, d2.y + b2.y,
                                       d2.z + b2.z, d2.w + b2.w);

        #pragma unroll
        for (int off = 16; off > 0; off >>= 1) {
            p1 += __shfl_xor_sync(0xffffffffu, p1, off);
            p2 += __shfl_xor_sync(0xffffffffu, p2, off);
        }
        if (lane == 0) { red1[warp] = p1; red2[warp] = p2; }
    }
    __syncthreads();
    if (tid == 0) {
        float e1 = 0.f, e2 = 0.f;
        #pragma unroll
        for (int w = 0; w < CN_WARPS; w++) { e1 += red1[w]; e2 += red2[w]; }
        sE[0] = e1; sE[1] = e2;
    }
    __syncthreads();
    if (!active) return;

    const float e1 = sE[0], e2 = sE[1];
    const float4* w0 = (const float4*)(sW + 0 * CN_DIM);
    const float4* w1 = (const float4*)(sW + 1 * CN_DIM);
    const float4* w2 = (const float4*)(sW + 2 * CN_DIM);

    // three independent dots t_l = x0 . w_l, 2 accumulators each for ILP
    float t0a = 0.f, t0b = 0.f, t1a = 0.f, t1b = 0.f, t2a = 0.f, t2b = 0.f;
    #pragma unroll
    for (int i = 0; i < CN_V_PER_LANE; i += 2) {
        float4 xa = x[i], xb = x[i + 1];
        float4 wa, wb;
        wa = w0[i * 32 + lane]; wb = w0[(i + 1) * 32 + lane];
        t0a = fmaf(xa.x, wa.x, t0a); t0a = fmaf(xa.y, wa.y, t0a);
        t0a = fmaf(xa.z, wa.z, t0a); t0a = fmaf(xa.w, wa.w, t0a);
        t0b = fmaf(xb.x, wb.x, t0b); t0b = fmaf(xb.y, wb.y, t0b);
        t0b = fmaf(xb.z, wb.z, t0b); t0b = fmaf(xb.w, wb.w, t0b);
        wa = w1[i * 32 + lane]; wb = w1[(i + 1) * 32 + lane];
        t1a = fmaf(xa.x, wa.x, t1a); t1a = fmaf(xa.y, wa.y, t1a);
        t1a = fmaf(xa.z, wa.z, t1a); t1a = fmaf(xa.w, wa.w, t1a);
        t1b = fmaf(xb.x, wb.x, t1b); t1b = fmaf(xb.y, wb.y, t1b);
        t1b = fmaf(xb.z, wb.z, t1b); t1b = fmaf(xb.w, wb.w, t1b);
        wa = w2[i * 32 + lane]; wb = w2[(i + 1) * 32 + lane];
        t2a = fmaf(xa.x, wa.x, t2a); t2a = fmaf(xa.y, wa.y, t2a);
        t2a = fmaf(xa.z, wa.z, t2a); t2a = fmaf(xa.w, wa.w, t2a);
        t2b = fmaf(xb.x, wb.x, t2b); t2b = fmaf(xb.y, wb.y, t2b);
        t2b = fmaf(xb.z, wb.z, t2b); t2b = fmaf(xb.w, wb.w, t2b);
    }
    float t0 = t0a + t0b, t1 = t1a + t1b, t2 = t2a + t2b;

    // warp reductions (independent, interleaved)
    #pragma unroll
    for (int off = 16; off > 0; off >>= 1) {
        t0 += __shfl_xor_sync(0xffffffffu, t0, off);
        t1 += __shfl_xor_sync(0xffffffffu, t1, off);
        t2 += __shfl_xor_sync(0xffffffffu, t2, off);
    }

    // scalar recurrence
    float c = 1.0f + t0;              // c1
    c = fmaf(c, t1, c) + e1;          // c2
    c = fmaf(c, t2, c) + e2;          // c3

    // out = c * x0 + D
    const float4* dv = (const float4*)sD;
    float4* __restrict__ orow = (float4*)(out + (size_t)row * CN_DIM);
    #pragma unroll
    for (int i = 0; i < CN_V_PER_LANE; i++) {
        float4 d = dv[i * 32 + lane];
        float4 o;
        o.x = fmaf(c, x[i].x, d.x);
        o.y = fmaf(c, x[i].y, d.y);
        o.z = fmaf(c, x[i].z, d.z);
        o.w = fmaf(c, x[i].w, d.w);
        orow[i * 32 + lane] = o;
    }
}

extern "C" void kernel_launch(void* const* d_in, const int* in_sizes, int n_in,
                              void* d_out, int out_size)
{
    const float* x0 = (const float*)d_in[0];
    const float* W  = (const float*)d_in[1];
    const float* B  = (const float*)d_in[2];
    float* out      = (float*)d_out;

    const int batch = in_sizes[0] / CN_DIM;
    const int grid  = (batch + CN_ROWS_PER_BLOCK - 1) / CN_ROWS_PER_BLOCK;

    crossnet_fused_kernel<<<grid, CN_THREADS>>>(x0, W, B, out, batch);
}

// round 10
// speedup vs baseline: 1.6013x; 1.0052x over previous
#include <cuda_runtime.h>

// CrossNet collapsed form (exact algebra):
//   xi_l = c_l * x0 + d_l,  d_l = B0+..+B_{l-1} (row-independent)
//   t_l  = x0 . w_l
//   c_{l+1} = c_l * (1 + t_l) + e_l,  e_l = d_l . w_l
//   out  = c_3 * x0 + D,  D = B0+B1+B2
//
// Single kernel, block-per-8-rows. Each block computes e1,e2,D during
// staging (W/B L2-resident). This round: occupancy 3->4 blocks/SM
// (launch_bounds reg budget 64) + streaming stores to keep x0 L2-resident.

#define CN_DIM 1024
#define CN_ORDER 3
#define CN_ROWS_PER_BLOCK 8
#define CN_THREADS 256
#define CN_WARPS (CN_THREADS / 32)
#define CN_VEC (CN_DIM / 4)        // 256 float4 per row
#define CN_V_PER_LANE 8            // 256 / 32 lanes

__global__ __launch_bounds__(CN_THREADS, 4)
void crossnet_fused_kernel(const float* __restrict__ x0,
                           const float* __restrict__ W,
                           const float* __restrict__ B,
                           float* __restrict__ out,
                           int batch)
{
    __shared__ float sW[CN_ORDER * CN_DIM];
    __shared__ float sD[CN_DIM];
    __shared__ float sE[2];
    __shared__ float red1[CN_WARPS];
    __shared__ float red2[CN_WARPS];

    const int tid  = threadIdx.x;
    const int warp = tid >> 5;
    const int lane = tid & 31;
    const int row  = blockIdx.x * CN_ROWS_PER_BLOCK + warp;
    const bool active = (row < batch);

    // Fire this warp's x0 row loads FIRST: 8 independent LDG.128 per lane
    // overlap the staging + barrier below.
    const float4* __restrict__ xrow =
        (const float4*)(x0 + (size_t)(active ? row : 0) * CN_DIM);
    float4 x[CN_V_PER_LANE];
    #pragma unroll
    for (int i = 0; i < CN_V_PER_LANE; i++)
        x[i] = xrow[i * 32 + lane];

    // ---- staging: W -> smem; compute D, e1, e2 from B/W (L2-hit reads) ----
    {
        const int i = tid;  // CN_VEC == CN_THREADS: one float4 per thread
        const float4* gW = (const float4*)W;
        float4 w0 = gW[i];
        float4 w1 = gW[CN_VEC + i];
        float4 w2 = gW[2 * CN_VEC + i];
        ((float4*)sW)[i]              = w0;
        ((float4*)sW)[CN_VEC + i]     = w1;
        ((float4*)sW)[2 * CN_VEC + i] = w2;

        const float4* gB = (const float4*)B;
        float4 b0 = gB[i];
        float4 b1 = gB[CN_VEC + i];
        float4 b2 = gB[2 * CN_VEC + i];

        // e1 = B0 . w1
        float p1 = 0.f;
        p1 = fmaf(b0.x, w1.x, p1); p1 = fmaf(b0.y, w1.y, p1);
        p1 = fmaf(b0.z, w1.z, p1); p1 = fmaf(b0.w, w1.w, p1);
        // d2 = B0 + B1 ; e2 = d2 . w2
        float4 d2 = make_float4(b0.x + b1.x, b0.y + b1.y, b0.z + b1.z, b0.w + b1.w);
        float p2 = 0.f;
        p2 = fmaf(d2.x, w2.x, p2); p2 = fmaf(d2.y, w2.y, p2);
        p2 = fmaf(d2.z, w2.z, p2); p2 = fmaf(d2.w, w2.w, p2);
        // D = d2 + B2
        ((float4*)sD)[i] = make_float4(d2.x + b2.x, d2.y + b2.y,
                                       d2.z + b2.z, d2.w + b2.w);

        #pragma unroll
        for (int off = 16; off > 0; off >>= 1) {
            p1 += __shfl_xor_sync(0xffffffffu, p1, off);
            p2 += __shfl_xor_sync(0xffffffffu, p2, off);
        }
        if (lane == 0) { red1[warp] = p1; red2[warp] = p2; }
    }
    __syncthreads();
    if (tid == 0) {
        float e1 = 0.f, e2 = 0.f;
        #pragma unroll
        for (int w = 0; w < CN_WARPS; w++) { e1 += red1[w]; e2 += red2[w]; }
        sE[0] = e1; sE[1] = e2;
    }
    __syncthreads();
    if (!active) return;

    const float e1 = sE[0], e2 = sE[1];
    const float4* w0 = (const float4*)(sW + 0 * CN_DIM);
    const float4* w1 = (const float4*)(sW + 1 * CN_DIM);
    const float4* w2 = (const float4*)(sW + 2 * CN_DIM);

    // three independent dots t_l = x0 . w_l, 2 accumulators each for ILP
    float t0a = 0.f, t0b = 0.f, t1a = 0.f, t1b = 0.f, t2a = 0.f, t2b = 0.f;
    #pragma unroll
    for (int i = 0; i < CN_V_PER_LANE; i += 2) {
        float4 xa = x[i], xb = x[i + 1];
        float4 wa, wb;
        wa = w0[i * 32 + lane]; wb = w0[(i + 1) * 32 + lane];
        t0a = fmaf(xa.x, wa.x, t0a); t0a = fmaf(xa.y, wa.y, t0a);
        t0a = fmaf(xa.z, wa.z, t0a); t0a = fmaf(xa.w, wa.w, t0a);
        t0b = fmaf(xb.x, wb.x, t0b); t0b = fmaf(xb.y, wb.y, t0b);
        t0b = fmaf(xb.z, wb.z, t0b); t0b = fmaf(xb.w, wb.w, t0b);
        wa = w1[i * 32 + lane]; wb = w1[(i + 1) * 32 + lane];
        t1a = fmaf(xa.x, wa.x, t1a); t1a = fmaf(xa.y, wa.y, t1a);
        t1a = fmaf(xa.z, wa.z, t1a); t1a = fmaf(xa.w, wa.w, t1a);
        t1b = fmaf(xb.x, wb.x, t1b); t1b = fmaf(xb.y, wb.y, t1b);
        t1b = fmaf(xb.z, wb.z, t1b); t1b = fmaf(xb.w, wb.w, t1b);
        wa = w2[i * 32 + lane]; wb = w2[(i + 1) * 32 + lane];
        t2a = fmaf(xa.x, wa.x, t2a); t2a = fmaf(xa.y, wa.y, t2a);
        t2a = fmaf(xa.z, wa.z, t2a); t2a = fmaf(xa.w, wa.w, t2a);
        t2b = fmaf(xb.x, wb.x, t2b); t2b = fmaf(xb.y, wb.y, t2b);
        t2b = fmaf(xb.z, wb.z, t2b); t2b = fmaf(xb.w, wb.w, t2b);
    }
    float t0 = t0a + t0b, t1 = t1a + t1b, t2 = t2a + t2b;

    // warp reductions (independent, interleaved)
    #pragma unroll
    for (int off = 16; off > 0; off >>= 1) {
        t0 += __shfl_xor_sync(0xffffffffu, t0, off);
        t1 += __shfl_xor_sync(0xffffffffu, t1, off);
        t2 += __shfl_xor_sync(0xffffffffu, t2, off);
    }

    // scalar recurrence
    float c = 1.0f + t0;              // c1
    c = fmaf(c, t1, c) + e1;          // c2
    c = fmaf(c, t2, c) + e2;          // c3

    // out = c * x0 + D  (streaming stores: don't evict x0 from L2)
    const float4* dv = (const float4*)sD;
    float4* __restrict__ orow = (float4*)(out + (size_t)row * CN_DIM);
    #pragma unroll
    for (int i = 0; i < CN_V_PER_LANE; i++) {
        float4 d = dv[i * 32 + lane];
        float4 o;
        o.x = fmaf(c, x[i].x, d.x);
        o.y = fmaf(c, x[i].y, d.y);
        o.z = fmaf(c, x[i].z, d.z);
        o.w = fmaf(c, x[i].w, d.w);
        __stcs(&orow[i * 32 + lane], o);
    }
}

extern "C" void kernel_launch(void* const* d_in, const int* in_sizes, int n_in,
                              void* d_out, int out_size)
{
    const float* x0 = (const float*)d_in[0];
    const float* W  = (const float*)d_in[1];
    const float* B  = (const float*)d_in[2];
    float* out      = (float*)d_out;

    const int batch = in_sizes[0] / CN_DIM;
    const int grid  = (batch + CN_ROWS_PER_BLOCK - 1) / CN_ROWS_PER_BLOCK;

    crossnet_fused_kernel<<<grid, CN_THREADS>>>(x0, W, B, out, batch);
}